// round 14
// baseline (speedup 1.0000x reference)
#include <cuda_runtime.h>
#include <math.h>
#include <float.h>
#include <stdint.h>

#define N_NODES 16384
#define D 128
#define BATCH 4
#define WPRIME (0.05f/1.05f)
#define EMAX 98304

#define KS 74
#define PAIRS (N_NODES / 2)
#define STAGES 4
#define SROW 136
#define STAGE_F (24 * SROW)
#define GSMEM (STAGES * STAGE_F * 4)

// ---------------- device scratch ----------------
__device__ float g_Rm[BATCH * D * D];
__device__ float g_Rp[(size_t)BATCH * KS * D * D];
__device__ int   g_rowptr[N_NODES + 1];
__device__ float g_partial[BATCH];
__device__ float g_pan[(size_t)BATCH * N_NODES * 1024];
__device__ float4 g_edgev[(size_t)BATCH * EMAX];
__device__ float g_geo[(size_t)BATCH * N_NODES * 12];

__device__ __forceinline__ uint32_t tf32c(float f) {
    uint32_t u; asm("cvt.rna.tf32.f32 %0, %1;" : "=r"(u) : "f"(f)); return u;
}
__device__ __forceinline__ float tf32f(float f) {
    return __uint_as_float(tf32c(f));
}

// ---------------- K1: CSR row pointers ----------------
__global__ void rowptr_kernel(const int* __restrict__ e0, int E) {
    int n = blockIdx.x * blockDim.x + threadIdx.x;
    if (n > N_NODES) return;
    int lo = 0, hi = E;
    while (lo < hi) {
        int mid = (lo + hi) >> 1;
        if (e0[mid] < n) lo = mid + 1; else hi = mid;
    }
    g_rowptr[n] = lo;
}

// ---------------- K1b: per-node geometry ----------------
__global__ void geom_kernel(const float* __restrict__ x, const int* __restrict__ e1arr) {
    const int n = blockIdx.x * blockDim.x + threadIdx.x;
    const int b = blockIdx.y;
    if (n >= N_NODES) return;

    const float* xb = x + (size_t)b * N_NODES * 3;
    const float xn0 = xb[3 * n], xn1 = xb[3 * n + 1], xn2 = xb[3 * n + 2];
    float4* ev = g_edgev + (size_t)b * EMAX;

    float deg = 0.f, s0 = 0.f, s1 = 0.f, s2 = 0.f, G = 0.f;
    float c00 = 0.f, c01 = 0.f, c02 = 0.f, c11 = 0.f, c12 = 0.f, c22 = 0.f;

    const int eBeg = g_rowptr[n], eEnd = g_rowptr[n + 1];
    for (int e = eBeg; e < eEnd; ++e) {
        const int m = e1arr[e];
        const float v0 = xn0 - xb[3 * m];
        const float v1 = xn1 - xb[3 * m + 1];
        const float v2 = xn2 - xb[3 * m + 2];
        ev[e] = make_float4(v0, v1, v2, 0.0f);
        deg += 1.0f; s0 += v0; s1 += v1; s2 += v2;
        const float vv = v0 * v0 + v1 * v1 + v2 * v2;
        G += vv;
        c00 += vv - v0 * v0; c01 -= v0 * v1; c02 -= v0 * v2;
        c11 += vv - v1 * v1; c12 -= v1 * v2; c22 += vv - v2 * v2;
    }

    const float l00 = sqrtf(c00);
    const float il00 = 1.0f / l00;
    const float l10 = c01 * il00, l20 = c02 * il00;
    const float l11 = sqrtf(c11 - l10 * l10);
    const float il11 = 1.0f / l11;
    const float l21 = (c12 - l20 * l10) * il11;
    const float l22 = sqrtf(c22 - l20 * l20 - l21 * l21);
    const float il22 = 1.0f / l22;
    const float Ginv = (G < 1e-6f) ? 0.0f : 1.0f / G;

    float* ge = g_geo + ((size_t)b * N_NODES + n) * 12;
    ge[0] = deg; ge[1] = s0; ge[2] = s1; ge[3] = s2;
    ge[4] = il00; ge[5] = l10; ge[6] = il11;
    ge[7] = l20; ge[8] = l21; ge[9] = il22;
    ge[10] = WPRIME * Ginv; ge[11] = 0.0f;
}

// ---------------- K2a: build panels — one WARP per node, float4 per lane ----------------
__global__ void __launch_bounds__(256)
build_kernel(const float* __restrict__ J, const int* __restrict__ e1arr) {
    const int b = blockIdx.y;
    const int warp = threadIdx.x >> 5;
    const int lane = threadIdx.x & 31;
    const int n = blockIdx.x * 8 + warp;
    const int c4 = lane * 4;                       // columns c4..c4+3

    const float* Jb = J + (size_t)b * N_NODES * 3 * D;
    const float4* ev = g_edgev + (size_t)b * EMAX;

    const float* JnR = Jb + (size_t)(3 * n) * D + c4;
    const float4 Jn0 = *(const float4*)(JnR);
    const float4 Jn1 = *(const float4*)(JnR + D);
    const float4 Jn2 = *(const float4*)(JnR + 2 * D);

    float4 nb0 = {0,0,0,0}, nb1 = {0,0,0,0}, nb2 = {0,0,0,0};
    float4 T0 = {0,0,0,0}, T1 = {0,0,0,0}, T2 = {0,0,0,0}, uu = {0,0,0,0};

    const int eBeg = g_rowptr[n], eEnd = g_rowptr[n + 1];
    const int degn = eEnd - eBeg;

#define ACC_NEIGH(v, m0, m1, m2)                                           \
    do {                                                                   \
        nb0.x += m0.x; nb0.y += m0.y; nb0.z += m0.z; nb0.w += m0.w;        \
        nb1.x += m1.x; nb1.y += m1.y; nb1.z += m1.z; nb1.w += m1.w;        \
        nb2.x += m2.x; nb2.y += m2.y; nb2.z += m2.z; nb2.w += m2.w;        \
        T0.x += v.y * m2.x - v.z * m1.x;  T0.y += v.y * m2.y - v.z * m1.y; \
        T0.z += v.y * m2.z - v.z * m1.z;  T0.w += v.y * m2.w - v.z * m1.w; \
        T1.x += v.z * m0.x - v.x * m2.x;  T1.y += v.z * m0.y - v.x * m2.y; \
        T1.z += v.z * m0.z - v.x * m2.z;  T1.w += v.z * m0.w - v.x * m2.w; \
        T2.x += v.x * m1.x - v.y * m0.x;  T2.y += v.x * m1.y - v.y * m0.y; \
        T2.z += v.x * m1.z - v.y * m0.z;  T2.w += v.x * m1.w - v.y * m0.w; \
        uu.x += v.x * m0.x + v.y * m1.x + v.z * m2.x;                      \
        uu.y += v.x * m0.y + v.y * m1.y + v.z * m2.y;                      \
        uu.z += v.x * m0.z + v.y * m1.z + v.z * m2.z;                      \
        uu.w += v.x * m0.w + v.y * m1.w + v.z * m2.w;                      \
    } while (0)

    if (degn == 6) {
        int mm[6];
#pragma unroll
        for (int i = 0; i < 6; i++) mm[i] = e1arr[eBeg + i];
        float4 vv6[6];
#pragma unroll
        for (int i = 0; i < 6; i++) vv6[i] = ev[eBeg + i];
#pragma unroll
        for (int i = 0; i < 6; i += 2) {
            const float* JmA = Jb + (size_t)(3 * mm[i]) * D + c4;
            const float* JmB = Jb + (size_t)(3 * mm[i + 1]) * D + c4;
            const float4 a0 = *(const float4*)(JmA);
            const float4 a1 = *(const float4*)(JmA + D);
            const float4 a2 = *(const float4*)(JmA + 2 * D);
            const float4 b0 = *(const float4*)(JmB);
            const float4 b1 = *(const float4*)(JmB + D);
            const float4 b2 = *(const float4*)(JmB + 2 * D);
            { const float4 v = vv6[i];     ACC_NEIGH(v, a0, a1, a2); }
            { const float4 v = vv6[i + 1]; ACC_NEIGH(v, b0, b1, b2); }
        }
    } else {
        for (int e = eBeg; e < eEnd; ++e) {
            const int m = e1arr[e];
            const float4 v = ev[e];
            const float* Jm = Jb + (size_t)(3 * m) * D + c4;
            const float4 m0 = *(const float4*)(Jm);
            const float4 m1 = *(const float4*)(Jm + D);
            const float4 m2 = *(const float4*)(Jm + 2 * D);
            ACC_NEIGH(v, m0, m1, m2);
        }
    }
#undef ACC_NEIGH

    const float* ge = g_geo + ((size_t)b * N_NODES + n) * 12;
    const float deg = ge[0], s0 = ge[1], s1 = ge[2], s2 = ge[3];
    const float il00 = ge[4], l10 = ge[5], il11 = ge[6];
    const float l20 = ge[7], l21 = ge[8], il22 = ge[9];
    const float wGinv = ge[10];

    float* P = g_pan + ((size_t)b * N_NODES + n) * 1024 + c4;
    float4 oZ0, oZ1, oZ2, oy, oL0, oL1, oL2, og;

#define COL(F)                                                              \
    {                                                                       \
        const float jn0 = Jn0.F, jn1 = Jn1.F, jn2 = Jn2.F;                  \
        const float LJ0 = 2.0f * (deg * jn0 - nb0.F);                       \
        const float LJ1 = 2.0f * (deg * jn1 - nb1.F);                       \
        const float LJ2 = 2.0f * (deg * jn2 - nb2.F);                       \
        const float B0 = T0.F + s2 * jn1 - s1 * jn2;                        \
        const float B1 = T1.F - s2 * jn0 + s0 * jn2;                        \
        const float B2 = T2.F + s1 * jn0 - s0 * jn1;                        \
        const float y = uu.F - (s0 * jn0 + s1 * jn1 + s2 * jn2);            \
        const float Z0 = B0 * il00;                                         \
        const float Z1 = (B1 - l10 * Z0) * il11;                            \
        const float Z2 = (B2 - l20 * Z0 - l21 * Z1) * il22;                 \
        oZ0.F = tf32f(Z0); oZ1.F = tf32f(Z1); oZ2.F = tf32f(Z2);            \
        oy.F = tf32f(y);                                                    \
        oL0.F = tf32f(LJ0); oL1.F = tf32f(LJ1); oL2.F = tf32f(LJ2);         \
        og.F = tf32f(-wGinv * y);                                           \
    }
    COL(x) COL(y) COL(z) COL(w)
#undef COL

    *(float4*)(P + 0 * 128) = oZ0;  *(float4*)(P + 1 * 128) = oZ1;
    *(float4*)(P + 2 * 128) = oZ2;  *(float4*)(P + 3 * 128) = oy;
    *(float4*)(P + 4 * 128) = oL0;  *(float4*)(P + 5 * 128) = oL1;
    *(float4*)(P + 6 * 128) = oL2;  *(float4*)(P + 7 * 128) = og;
}

// ---------------- K2b: TF32 split-K GEMM (unchanged, known good) ----------------
__device__ __forceinline__ void cp_async16(void* dst_smem, const void* src) {
    uint32_t d = (uint32_t)__cvta_generic_to_shared(dst_smem);
    asm volatile("cp.async.cg.shared.global [%0], [%1], 16;" :: "r"(d), "l"(src));
}
__device__ __forceinline__ void cp_commit() { asm volatile("cp.async.commit_group;"); }
template<int NN> __device__ __forceinline__ void cp_wait() {
    asm volatile("cp.async.wait_group %0;" :: "n"(NN));
}
__device__ __forceinline__ void mma_tf32(float* d, uint32_t a0, uint32_t a1,
                                         uint32_t a2, uint32_t a3,
                                         uint32_t b0, uint32_t b1) {
    asm volatile(
        "mma.sync.aligned.m16n8k8.row.col.f32.tf32.tf32.f32 "
        "{%0,%1,%2,%3}, {%4,%5,%6,%7}, {%8,%9}, {%0,%1,%2,%3};"
        : "+f"(d[0]), "+f"(d[1]), "+f"(d[2]), "+f"(d[3])
        : "r"(a0), "r"(a1), "r"(a2), "r"(a3), "r"(b0), "r"(b1));
}

__global__ void __launch_bounds__(256, 2)
gemm_kernel(const float* __restrict__ J) {
    extern __shared__ float smg[];

    const int b = blockIdx.y, ks = blockIdx.x;
    const int t = threadIdx.x;
    const int wid = t >> 5, lane = t & 31;
    const int wm = (wid >> 2) * 64;
    const int wn = (wid & 3) * 32;
    const int r0 = lane >> 2, kc = lane & 3;

    const int pbeg = (ks * PAIRS) / KS;
    const int pend = ((ks + 1) * PAIRS) / KS;
    const int NITv = pend - pbeg;
    const int nodeBase = 2 * pbeg;

    const float* Jb = J + (size_t)b * N_NODES * 3 * D;
    const float* Pb = g_pan + ((size_t)b * N_NODES + nodeBase) * 1024;

    for (int idx = t; idx < STAGES * 2 * SROW; idx += 256) {
        const int s = idx / (2 * SROW);
        const int rem = idx - s * 2 * SROW;
        const int row = (rem < SROW) ? 7 : 19;
        smg[s * STAGE_F + row * SROW + (rem % SROW)] = 0.0f;
    }

    const int      brow0 = (kc < 3) ? 8 + kc : 3;
    const uint32_t bmsk0 = (kc < 3) ? 0u : 0x80000000u;
    const int      brow1 = (kc < 2) ? 4 + kc : ((kc == 2) ? 11 : 7);
    const uint32_t bmsk1 = (kc < 2) ? 0x80000000u : 0u;

    float acc[4][4][4];
#pragma unroll
    for (int i = 0; i < 4; i++)
#pragma unroll
        for (int j = 0; j < 4; j++)
#pragma unroll
            for (int r = 0; r < 4; r++) acc[i][j][r] = 0.0f;

    const int prow = t >> 5;
    const int scol = (t & 31) * 4;
    const int srowP = (prow < 4) ? 3 + prow : 4 + prow;

    auto issue = [&](int it) {
        const int stg = it & (STAGES - 1);
        float* SB = smg + stg * STAGE_F;
        const float* p0 = Pb + (size_t)(2 * it) * 1024;
        cp_async16(SB + srowP * SROW + scol, p0 + t * 4);
        cp_async16(SB + (12 + srowP) * SROW + scol, p0 + 1024 + t * 4);
        if (t < 96) {
            const float* j0 = Jb + (size_t)(3 * (nodeBase + 2 * it)) * D;
            cp_async16(SB + prow * SROW + scol, j0 + t * 4);
            cp_async16(SB + (12 + prow) * SROW + scol, j0 + 384 + t * 4);
        }
    };

    for (int s = 0; s < STAGES - 1; s++) { if (s < NITv) issue(s); cp_commit(); }

    for (int it = 0; it < NITv; ++it) {
        const int stg = it & (STAGES - 1);
        if (it + STAGES - 1 < NITv) issue(it + STAGES - 1);
        cp_commit();
        cp_wait<STAGES - 1>();
        __syncthreads();

        const float* S0 = smg + stg * STAGE_F;
#pragma unroll
        for (int g = 0; g < 2; ++g) {
            const float* S = S0 + g * 12 * SROW;

            uint32_t bb[4][2];
#pragma unroll
            for (int nt = 0; nt < 4; nt++) {
                const int n = wn + nt * 8 + r0;
                bb[nt][0] = __float_as_uint(S[brow0 * SROW + n]) ^ bmsk0;
                bb[nt][1] = __float_as_uint(S[brow1 * SROW + n]) ^ bmsk1;
            }
#pragma unroll
            for (int mt = 0; mt < 4; mt++) {
                const int m = wm + mt * 16 + r0;
                const uint32_t a0 = tf32c(S[kc * SROW + m]);
                const uint32_t a1 = tf32c(S[kc * SROW + m + 8]);
                const uint32_t a2 = __float_as_uint(S[(kc + 4) * SROW + m]);
                const uint32_t a3 = __float_as_uint(S[(kc + 4) * SROW + m + 8]);
#pragma unroll
                for (int nt = 0; nt < 4; nt++)
                    mma_tf32(acc[mt][nt], a0, a1, a2, a3, bb[nt][0], bb[nt][1]);
            }
        }
        __syncthreads();
    }

    float* out = g_Rp + (((size_t)b * KS + ks) << 14);
#pragma unroll
    for (int mt = 0; mt < 4; mt++) {
        const int m = wm + mt * 16 + r0;
#pragma unroll
        for (int nt = 0; nt < 4; nt++) {
            const int n = wn + nt * 8 + 2 * kc;
            *(float2*)&out[m * 128 + n]       = make_float2(acc[mt][nt][0], acc[mt][nt][1]);
            *(float2*)&out[(m + 8) * 128 + n] = make_float2(acc[mt][nt][2], acc[mt][nt][3]);
        }
    }
}

// ---------------- K2c: reduce split-K partials (float4) ----------------
__global__ void reduce_kernel() {
    const int idx = blockIdx.x * 256 + threadIdx.x;   // 0..16383 float4 slots
    const int b = idx >> 12;                           // 4096 float4 per batch
    const int e = idx & 4095;
    const float4* p = (const float4*)(g_Rp + ((size_t)b * KS << 14)) + e;
    float4 s = {0, 0, 0, 0};
#pragma unroll 8
    for (int k = 0; k < KS; k++) {
        const float4 v = p[(size_t)k << 12];
        s.x += v.x; s.y += v.y; s.z += v.z; s.w += v.w;
    }
    ((float4*)g_Rm)[idx] = s;
}

// ---------------- 256-thread reductions for eigen tail ----------------
__device__ __forceinline__ float brs256(float v, float* red) {
#pragma unroll
    for (int off = 16; off > 0; off >>= 1) v += __shfl_down_sync(0xffffffffu, v, off);
    if ((threadIdx.x & 31) == 0) red[threadIdx.x >> 5] = v;
    __syncthreads();
    float s = 0.f;
#pragma unroll
    for (int i = 0; i < 8; i++) s += red[i];
    __syncthreads();
    return s;
}
__device__ __forceinline__ float brmin256(float v, float* red) {
#pragma unroll
    for (int off = 16; off > 0; off >>= 1) v = fminf(v, __shfl_down_sync(0xffffffffu, v, off));
    if ((threadIdx.x & 31) == 0) red[threadIdx.x >> 5] = v;
    __syncthreads();
    float s = red[0];
#pragma unroll
    for (int i = 1; i < 8; i++) s = fminf(s, red[i]);
    __syncthreads();
    return s;
}
__device__ __forceinline__ float brmax256(float v, float* red) {
#pragma unroll
    for (int off = 16; off > 0; off >>= 1) v = fmaxf(v, __shfl_down_sync(0xffffffffu, v, off));
    if ((threadIdx.x & 31) == 0) red[threadIdx.x >> 5] = v;
    __syncthreads();
    float s = red[0];
#pragma unroll
    for (int i = 1; i < 8; i++) s = fmaxf(s, red[i]);
    __syncthreads();
    return s;
}

// ---------------- K3: row-split Householder, 2 barriers/iter + split twisted Sturm ----------------
#define ASTR 132
#define SMEM_EIG ((128 * ASTR + 3 * 128 + 256 + 2 * 128 + 96) * 4)

__global__ void __launch_bounds__(256)
eigen_kernel() {
    extern __shared__ float smE[];
    float* A  = smE;                  // 128 x ASTR
    float* xA = A + 128 * ASTR;       // 128
    float* xB = xA + 128;             // 128
    float* qq = xB + 128;             // 128
    float* pp = qq + 128;             // 256 (half-dot partials; later e2)
    float* dd = pp + 256;             // 128
    float* ee = dd + 128;             // 128
    float* red = ee + 128;            // 96: loop parity banks [0..63], tail [64..95]

    const int b = blockIdx.x;
    const int t = threadIdx.x;
    const int r = t & 127;
    const int h = t >> 7;
    const int w = t >> 5, lane = t & 31;
    const int cbeg = h << 6;
    const float* R = g_Rm + (size_t)b * D * D;

    for (int i = h; i < 128; i += 2)
        A[i * ASTR + r] = 0.5f * (R[i * 128 + r] + R[r * 128 + i]);
    __syncthreads();

    // bootstrap: x = col 0; pp[t] = half-row dot; keep register copy pnreg
    float pnreg;
    {
        if (h == 0) xA[r] = (r > 0) ? A[r * ASTR] : 0.0f;
        __syncthreads();
        const float4* Ar4 = (const float4*)(A + r * ASTR + cbeg);
        const float4* X4  = (const float4*)(xA + cbeg);
        float pa[4] = {0.f, 0.f, 0.f, 0.f};
#pragma unroll 4
        for (int q = 0; q < 16; q++) {
            const float4 a = Ar4[q], xv = X4[q];
            pa[q & 3] += a.x * xv.x + a.y * xv.y + a.z * xv.z + a.w * xv.w;
        }
        pnreg = (pa[0] + pa[1]) + (pa[2] + pa[3]);
        pp[t] = pnreg;
        __syncthreads();
    }

    for (int k = 0; k < 126; k++) {
        float* xx = (k & 1) ? xB : xA;
        float* xn = (k & 1) ? xA : xB;
        float* sA = red + (k & 1) * 32;      // 8 slots ws, 8 slots kv2
        float* sB = sA + 8;

        const float xi = xx[r];              // ordered by prev barrier (2)
        float ws  = (h == 0) ? xi * xi : 0.0f;
        float kv2 = xi * pnreg;              // own register — no cross-thread read
#pragma unroll
        for (int off = 16; off > 0; off >>= 1) {
            ws  += __shfl_down_sync(0xffffffffu, ws, off);
            kv2 += __shfl_down_sync(0xffffffffu, kv2, off);
        }
        if (lane == 0) { sA[w] = ws; sB[w] = kv2; }
        __syncthreads();                                  // (1)
        float sig = 0.f, S2 = 0.f;
#pragma unroll
        for (int i = 0; i < 8; i++) { sig += sA[i]; S2 += sB[i]; }
        const float x0 = xx[k + 1];
        const float nrm = sqrtf(sig);
        const float alpha = (x0 >= 0.0f) ? -nrm : nrm;
        const float H = sig - alpha * x0;
        const float invH = (H > 1e-32f) ? 1.0f / H : 0.0f;
        if (t == 0) ee[k + 1] = alpha;
        const float praw_k1 = pp[k + 1] + pp[k + 1 + 128];       // ordered by (1)
        const float dk1 = A[(k + 1) * ASTR + (k + 1)];           // ordered by (1)
        const float uAu = S2 - 2.0f * alpha * praw_k1 + alpha * alpha * dk1;
        const float Kc = uAu * invH * 0.5f * invH;
        const float ut = xi - ((r == k + 1) ? alpha : 0.0f);
        const float pcomb = pp[r] + pp[r + 128];
        const float p = (r > k) ? (pcomb - alpha * A[r * ASTR + (k + 1)]) * invH : 0.0f;
        const float qt = (r > k) ? (p - Kc * ut) : 0.0f;
        const float uk1 = x0 - alpha;
        const float pk1 = (praw_k1 - alpha * dk1) * invH;
        const float qk1 = pk1 - Kc * uk1;
        if (h == 0) {
            qq[r] = qt;
            xn[r] = (r >= k + 2) ? (A[r * ASTR + (k + 1)] - ut * qk1 - qt * uk1) : 0.0f;
        }
        __syncthreads();                                  // (2)
        // fused half-pass: rank-2 update + next half-dot
        {
            const int j0 = (k + 1) & ~3;
            const int js = (j0 > cbeg) ? j0 : cbeg;
            const int je = cbeg + 64;
            float pn[4] = {0.f, 0.f, 0.f, 0.f};
            if (r > k && js < je) {
                const int m = (je - js) >> 2;
                float4* Ar4 = (float4*)(A + r * ASTR + js);
                const float4* U4 = (const float4*)(xx + js);
                const float4* Q4 = (const float4*)(qq + js);
                const float4* N4 = (const float4*)(xn + js);
#pragma unroll 4
                for (int q = 0; q < m; q++) {
                    float4 a = Ar4[q];
                    const float4 u4 = U4[q], q4 = Q4[q], n4 = N4[q];
                    a.x -= ut * q4.x + qt * u4.x;
                    a.y -= ut * q4.y + qt * u4.y;
                    a.z -= ut * q4.z + qt * u4.z;
                    a.w -= ut * q4.w + qt * u4.w;
                    pn[q & 3] += a.x * n4.x + a.y * n4.y + a.z * n4.z + a.w * n4.w;
                    Ar4[q] = a;
                }
                if (k + 1 >= js && k + 1 < je)
                    A[r * ASTR + (k + 1)] += alpha * qt;   // xx held x, not u
            }
            pnreg = (pn[0] + pn[1]) + (pn[2] + pn[3]);
            pp[t] = pnreg;
        }
        // next iteration's barrier (1) orders the pass
    }
    __syncthreads();

    if (h == 0) {
        dd[r] = A[r * ASTR + r];
        if (r == 0) { ee[0] = 0.0f; ee[127] = A[127 * ASTR + 126]; }
    }
    __syncthreads();
    float* e2 = pp;
    if (h == 0) e2[r] = ee[r] * ee[r];
    float gl_in = FLT_MAX, gu_in = -FLT_MAX;
    if (h == 0) {
        const float rad = fabsf(ee[r]) + ((r < 127) ? fabsf(ee[r + 1]) : 0.0f);
        gl_in = dd[r] - rad;
        gu_in = dd[r] + rad;
    }
    const float gl = brmin256(gl_in, red + 64);
    const float gu = brmax256(gu_in, red + 64);
    __syncthreads();

    const float pivmin = fmaxf(1e-12f * fmaxf(fabsf(gl), fabsf(gu)), 1e-36f);
    float* qx0 = A;
    int*   cx0 = (int*)(A + 1024);
    float lo = gl, hi = gu;
    for (int iter = 0; iter < 26; ++iter) {
        const int par = (iter & 1) * 256;
        float* qx = qx0 + par;
        int*   cx = cx0 + par;
        const float mid = 0.5f * (lo + hi);
        if (h == 0) {
            float qf = dd[0] - mid;
            int cf = (qf < 0.0f);
#pragma unroll 3
            for (int j = 1; j <= 63; j++) {
                if (fabsf(qf) < pivmin) qf = -pivmin;
                qf = dd[j] - mid - __fdividef(e2[j], qf);
                cf += (qf < 0.0f);
            }
            if (fabsf(qf) < pivmin) qf = -pivmin;
            qx[r] = qf; cx[r] = cf;
        } else {
            float qb = dd[127] - mid;
            int cb = (qb < 0.0f);
#pragma unroll 3
            for (int i = 126; i >= 65; i--) {
                if (fabsf(qb) < pivmin) qb = -pivmin;
                qb = dd[i] - mid - __fdividef(e2[i + 1], qb);
                cb += (qb < 0.0f);
            }
            if (fabsf(qb) < pivmin) qb = -pivmin;
            qx[128 + r] = qb; cx[128 + r] = cb;
        }
        __syncthreads();
        const float qf = qx[r], qb = qx[128 + r];
        const float gam = dd[64] - mid - __fdividef(e2[64], qf) - __fdividef(e2[65], qb);
        const int cnt = cx[r] + cx[128 + r] + (gam < 0.0f);
        if (cnt > r) hi = mid; else lo = mid;
    }
    const float lam = 0.5f * (lo + hi);
    const float v = (h == 0 && lam > 0.0f) ? sqrtf(lam) : 0.0f;
    __syncthreads();
    const float s = brs256(v, red + 64);
    if (t == 0) g_partial[b] = s;
}

// ---------------- K4: mean over batch ----------------
__global__ void finalize_kernel(float* out) {
    out[0] = 0.25f * (g_partial[0] + g_partial[1] + g_partial[2] + g_partial[3]);
}

// ---------------- launch ----------------
extern "C" void kernel_launch(void* const* d_in, const int* in_sizes, int n_in,
                              void* d_out, int out_size) {
    const float* x  = (const float*)d_in[0];
    const float* J  = (const float*)d_in[1];
    const int*   ei = (const int*)d_in[2];
    const int E = in_sizes[2] / 2;
    float* out = (float*)d_out;

    cudaFuncSetAttribute(eigen_kernel,
                         cudaFuncAttributeMaxDynamicSharedMemorySize, SMEM_EIG);
    cudaFuncSetAttribute(gemm_kernel,
                         cudaFuncAttributeMaxDynamicSharedMemorySize, GSMEM);

    rowptr_kernel<<<(N_NODES + 1 + 255) / 256, 256>>>(ei, E);

    dim3 ggeo((N_NODES + 127) / 128, BATCH);
    geom_kernel<<<ggeo, 128>>>(x, ei + E);

    dim3 gbuild(N_NODES / 8, BATCH);
    build_kernel<<<gbuild, 256>>>(J, ei + E);

    dim3 ggemm(KS, BATCH);
    gemm_kernel<<<ggemm, 256, GSMEM>>>(J);
    reduce_kernel<<<BATCH * D * D / 4 / 256, 256>>>();

    eigen_kernel<<<BATCH, 256, SMEM_EIG>>>();
    finalize_kernel<<<1, 1>>>(out);
}

// round 15
// speedup vs baseline: 1.0159x; 1.0159x over previous
#include <cuda_runtime.h>
#include <math.h>
#include <float.h>
#include <stdint.h>

#define N_NODES 16384
#define D 128
#define BATCH 4
#define WPRIME (0.05f/1.05f)
#define EMAX 98304

#define KS 74
#define PAIRS (N_NODES / 2)
#define STAGES 4
#define SROW 136
#define STAGE_F (24 * SROW)
#define GSMEM (STAGES * STAGE_F * 4)

// ---------------- device scratch ----------------
__device__ float g_Rm[BATCH * D * D];
__device__ float g_Rp[(size_t)BATCH * KS * D * D];
__device__ int   g_rowptr[N_NODES + 1];
__device__ float g_partial[BATCH];
__device__ float g_pan[(size_t)BATCH * N_NODES * 1024];
__device__ float4 g_edgev[(size_t)BATCH * EMAX];
__device__ float g_geo[(size_t)BATCH * N_NODES * 12];

__device__ __forceinline__ uint32_t tf32c(float f) {
    uint32_t u; asm("cvt.rna.tf32.f32 %0, %1;" : "=r"(u) : "f"(f)); return u;
}
__device__ __forceinline__ float tf32f(float f) {
    return __uint_as_float(tf32c(f));
}

// ---------------- K1: CSR row pointers ----------------
__global__ void rowptr_kernel(const int* __restrict__ e0, int E) {
    int n = blockIdx.x * blockDim.x + threadIdx.x;
    if (n > N_NODES) return;
    int lo = 0, hi = E;
    while (lo < hi) {
        int mid = (lo + hi) >> 1;
        if (e0[mid] < n) lo = mid + 1; else hi = mid;
    }
    g_rowptr[n] = lo;
}

// ---------------- K1b: per-node geometry ----------------
__global__ void geom_kernel(const float* __restrict__ x, const int* __restrict__ e1arr) {
    const int n = blockIdx.x * blockDim.x + threadIdx.x;
    const int b = blockIdx.y;
    if (n >= N_NODES) return;

    const float* xb = x + (size_t)b * N_NODES * 3;
    const float xn0 = xb[3 * n], xn1 = xb[3 * n + 1], xn2 = xb[3 * n + 2];
    float4* ev = g_edgev + (size_t)b * EMAX;

    float deg = 0.f, s0 = 0.f, s1 = 0.f, s2 = 0.f, G = 0.f;
    float c00 = 0.f, c01 = 0.f, c02 = 0.f, c11 = 0.f, c12 = 0.f, c22 = 0.f;

    const int eBeg = g_rowptr[n], eEnd = g_rowptr[n + 1];
    for (int e = eBeg; e < eEnd; ++e) {
        const int m = e1arr[e];
        const float v0 = xn0 - xb[3 * m];
        const float v1 = xn1 - xb[3 * m + 1];
        const float v2 = xn2 - xb[3 * m + 2];
        ev[e] = make_float4(v0, v1, v2, 0.0f);
        deg += 1.0f; s0 += v0; s1 += v1; s2 += v2;
        const float vv = v0 * v0 + v1 * v1 + v2 * v2;
        G += vv;
        c00 += vv - v0 * v0; c01 -= v0 * v1; c02 -= v0 * v2;
        c11 += vv - v1 * v1; c12 -= v1 * v2; c22 += vv - v2 * v2;
    }

    const float l00 = sqrtf(c00);
    const float il00 = 1.0f / l00;
    const float l10 = c01 * il00, l20 = c02 * il00;
    const float l11 = sqrtf(c11 - l10 * l10);
    const float il11 = 1.0f / l11;
    const float l21 = (c12 - l20 * l10) * il11;
    const float l22 = sqrtf(c22 - l20 * l20 - l21 * l21);
    const float il22 = 1.0f / l22;
    const float Ginv = (G < 1e-6f) ? 0.0f : 1.0f / G;

    float* ge = g_geo + ((size_t)b * N_NODES + n) * 12;
    ge[0] = deg; ge[1] = s0; ge[2] = s1; ge[3] = s2;
    ge[4] = il00; ge[5] = l10; ge[6] = il11;
    ge[7] = l20; ge[8] = l21; ge[9] = il22;
    ge[10] = WPRIME * Ginv; ge[11] = 0.0f;
}

// ---------------- K2a: build panels — one WARP per node, float4 per lane ----------------
__global__ void __launch_bounds__(256)
build_kernel(const float* __restrict__ J, const int* __restrict__ e1arr) {
    const int b = blockIdx.y;
    const int warp = threadIdx.x >> 5;
    const int lane = threadIdx.x & 31;
    const int n = blockIdx.x * 8 + warp;
    const int c4 = lane * 4;

    const float* Jb = J + (size_t)b * N_NODES * 3 * D;
    const float4* ev = g_edgev + (size_t)b * EMAX;

    const float* JnR = Jb + (size_t)(3 * n) * D + c4;
    const float4 Jn0 = *(const float4*)(JnR);
    const float4 Jn1 = *(const float4*)(JnR + D);
    const float4 Jn2 = *(const float4*)(JnR + 2 * D);

    float4 nb0 = {0,0,0,0}, nb1 = {0,0,0,0}, nb2 = {0,0,0,0};
    float4 T0 = {0,0,0,0}, T1 = {0,0,0,0}, T2 = {0,0,0,0}, uu = {0,0,0,0};

    const int eBeg = g_rowptr[n], eEnd = g_rowptr[n + 1];
    const int degn = eEnd - eBeg;

#define ACC_NEIGH(v, m0, m1, m2)                                           \
    do {                                                                   \
        nb0.x += m0.x; nb0.y += m0.y; nb0.z += m0.z; nb0.w += m0.w;        \
        nb1.x += m1.x; nb1.y += m1.y; nb1.z += m1.z; nb1.w += m1.w;        \
        nb2.x += m2.x; nb2.y += m2.y; nb2.z += m2.z; nb2.w += m2.w;        \
        T0.x += v.y * m2.x - v.z * m1.x;  T0.y += v.y * m2.y - v.z * m1.y; \
        T0.z += v.y * m2.z - v.z * m1.z;  T0.w += v.y * m2.w - v.z * m1.w; \
        T1.x += v.z * m0.x - v.x * m2.x;  T1.y += v.z * m0.y - v.x * m2.y; \
        T1.z += v.z * m0.z - v.x * m2.z;  T1.w += v.z * m0.w - v.x * m2.w; \
        T2.x += v.x * m1.x - v.y * m0.x;  T2.y += v.x * m1.y - v.y * m0.y; \
        T2.z += v.x * m1.z - v.y * m0.z;  T2.w += v.x * m1.w - v.y * m0.w; \
        uu.x += v.x * m0.x + v.y * m1.x + v.z * m2.x;                      \
        uu.y += v.x * m0.y + v.y * m1.y + v.z * m2.y;                      \
        uu.z += v.x * m0.z + v.y * m1.z + v.z * m2.z;                      \
        uu.w += v.x * m0.w + v.y * m1.w + v.z * m2.w;                      \
    } while (0)

    if (degn == 6) {
        int mm[6];
#pragma unroll
        for (int i = 0; i < 6; i++) mm[i] = e1arr[eBeg + i];
        float4 vv6[6];
#pragma unroll
        for (int i = 0; i < 6; i++) vv6[i] = ev[eBeg + i];
#pragma unroll
        for (int i = 0; i < 6; i += 2) {
            const float* JmA = Jb + (size_t)(3 * mm[i]) * D + c4;
            const float* JmB = Jb + (size_t)(3 * mm[i + 1]) * D + c4;
            const float4 a0 = *(const float4*)(JmA);
            const float4 a1 = *(const float4*)(JmA + D);
            const float4 a2 = *(const float4*)(JmA + 2 * D);
            const float4 b0 = *(const float4*)(JmB);
            const float4 b1 = *(const float4*)(JmB + D);
            const float4 b2 = *(const float4*)(JmB + 2 * D);
            { const float4 v = vv6[i];     ACC_NEIGH(v, a0, a1, a2); }
            { const float4 v = vv6[i + 1]; ACC_NEIGH(v, b0, b1, b2); }
        }
    } else {
        for (int e = eBeg; e < eEnd; ++e) {
            const int m = e1arr[e];
            const float4 v = ev[e];
            const float* Jm = Jb + (size_t)(3 * m) * D + c4;
            const float4 m0 = *(const float4*)(Jm);
            const float4 m1 = *(const float4*)(Jm + D);
            const float4 m2 = *(const float4*)(Jm + 2 * D);
            ACC_NEIGH(v, m0, m1, m2);
        }
    }
#undef ACC_NEIGH

    const float* ge = g_geo + ((size_t)b * N_NODES + n) * 12;
    const float deg = ge[0], s0 = ge[1], s1 = ge[2], s2 = ge[3];
    const float il00 = ge[4], l10 = ge[5], il11 = ge[6];
    const float l20 = ge[7], l21 = ge[8], il22 = ge[9];
    const float wGinv = ge[10];

    float* P = g_pan + ((size_t)b * N_NODES + n) * 1024 + c4;
    float4 oZ0, oZ1, oZ2, oy, oL0, oL1, oL2, og;

#define COL(F)                                                              \
    {                                                                       \
        const float jn0 = Jn0.F, jn1 = Jn1.F, jn2 = Jn2.F;                  \
        const float LJ0 = 2.0f * (deg * jn0 - nb0.F);                       \
        const float LJ1 = 2.0f * (deg * jn1 - nb1.F);                       \
        const float LJ2 = 2.0f * (deg * jn2 - nb2.F);                       \
        const float B0 = T0.F + s2 * jn1 - s1 * jn2;                        \
        const float B1 = T1.F - s2 * jn0 + s0 * jn2;                        \
        const float B2 = T2.F + s1 * jn0 - s0 * jn1;                        \
        const float y = uu.F - (s0 * jn0 + s1 * jn1 + s2 * jn2);            \
        const float Z0 = B0 * il00;                                         \
        const float Z1 = (B1 - l10 * Z0) * il11;                            \
        const float Z2 = (B2 - l20 * Z0 - l21 * Z1) * il22;                 \
        oZ0.F = tf32f(Z0); oZ1.F = tf32f(Z1); oZ2.F = tf32f(Z2);            \
        oy.F = tf32f(y);                                                    \
        oL0.F = tf32f(LJ0); oL1.F = tf32f(LJ1); oL2.F = tf32f(LJ2);         \
        og.F = tf32f(-wGinv * y);                                           \
    }
    COL(x) COL(y) COL(z) COL(w)
#undef COL

    *(float4*)(P + 0 * 128) = oZ0;  *(float4*)(P + 1 * 128) = oZ1;
    *(float4*)(P + 2 * 128) = oZ2;  *(float4*)(P + 3 * 128) = oy;
    *(float4*)(P + 4 * 128) = oL0;  *(float4*)(P + 5 * 128) = oL1;
    *(float4*)(P + 6 * 128) = oL2;  *(float4*)(P + 7 * 128) = og;
}

// ---------------- K2b: TF32 split-K GEMM (unchanged, known good) ----------------
__device__ __forceinline__ void cp_async16(void* dst_smem, const void* src) {
    uint32_t d = (uint32_t)__cvta_generic_to_shared(dst_smem);
    asm volatile("cp.async.cg.shared.global [%0], [%1], 16;" :: "r"(d), "l"(src));
}
__device__ __forceinline__ void cp_commit() { asm volatile("cp.async.commit_group;"); }
template<int NN> __device__ __forceinline__ void cp_wait() {
    asm volatile("cp.async.wait_group %0;" :: "n"(NN));
}
__device__ __forceinline__ void mma_tf32(float* d, uint32_t a0, uint32_t a1,
                                         uint32_t a2, uint32_t a3,
                                         uint32_t b0, uint32_t b1) {
    asm volatile(
        "mma.sync.aligned.m16n8k8.row.col.f32.tf32.tf32.f32 "
        "{%0,%1,%2,%3}, {%4,%5,%6,%7}, {%8,%9}, {%0,%1,%2,%3};"
        : "+f"(d[0]), "+f"(d[1]), "+f"(d[2]), "+f"(d[3])
        : "r"(a0), "r"(a1), "r"(a2), "r"(a3), "r"(b0), "r"(b1));
}

__global__ void __launch_bounds__(256, 2)
gemm_kernel(const float* __restrict__ J) {
    extern __shared__ float smg[];

    const int b = blockIdx.y, ks = blockIdx.x;
    const int t = threadIdx.x;
    const int wid = t >> 5, lane = t & 31;
    const int wm = (wid >> 2) * 64;
    const int wn = (wid & 3) * 32;
    const int r0 = lane >> 2, kc = lane & 3;

    const int pbeg = (ks * PAIRS) / KS;
    const int pend = ((ks + 1) * PAIRS) / KS;
    const int NITv = pend - pbeg;
    const int nodeBase = 2 * pbeg;

    const float* Jb = J + (size_t)b * N_NODES * 3 * D;
    const float* Pb = g_pan + ((size_t)b * N_NODES + nodeBase) * 1024;

    for (int idx = t; idx < STAGES * 2 * SROW; idx += 256) {
        const int s = idx / (2 * SROW);
        const int rem = idx - s * 2 * SROW;
        const int row = (rem < SROW) ? 7 : 19;
        smg[s * STAGE_F + row * SROW + (rem % SROW)] = 0.0f;
    }

    const int      brow0 = (kc < 3) ? 8 + kc : 3;
    const uint32_t bmsk0 = (kc < 3) ? 0u : 0x80000000u;
    const int      brow1 = (kc < 2) ? 4 + kc : ((kc == 2) ? 11 : 7);
    const uint32_t bmsk1 = (kc < 2) ? 0x80000000u : 0u;

    float acc[4][4][4];
#pragma unroll
    for (int i = 0; i < 4; i++)
#pragma unroll
        for (int j = 0; j < 4; j++)
#pragma unroll
            for (int r = 0; r < 4; r++) acc[i][j][r] = 0.0f;

    const int prow = t >> 5;
    const int scol = (t & 31) * 4;
    const int srowP = (prow < 4) ? 3 + prow : 4 + prow;

    auto issue = [&](int it) {
        const int stg = it & (STAGES - 1);
        float* SB = smg + stg * STAGE_F;
        const float* p0 = Pb + (size_t)(2 * it) * 1024;
        cp_async16(SB + srowP * SROW + scol, p0 + t * 4);
        cp_async16(SB + (12 + srowP) * SROW + scol, p0 + 1024 + t * 4);
        if (t < 96) {
            const float* j0 = Jb + (size_t)(3 * (nodeBase + 2 * it)) * D;
            cp_async16(SB + prow * SROW + scol, j0 + t * 4);
            cp_async16(SB + (12 + prow) * SROW + scol, j0 + 384 + t * 4);
        }
    };

    for (int s = 0; s < STAGES - 1; s++) { if (s < NITv) issue(s); cp_commit(); }

    for (int it = 0; it < NITv; ++it) {
        const int stg = it & (STAGES - 1);
        if (it + STAGES - 1 < NITv) issue(it + STAGES - 1);
        cp_commit();
        cp_wait<STAGES - 1>();
        __syncthreads();

        const float* S0 = smg + stg * STAGE_F;
#pragma unroll
        for (int g = 0; g < 2; ++g) {
            const float* S = S0 + g * 12 * SROW;

            uint32_t bb[4][2];
#pragma unroll
            for (int nt = 0; nt < 4; nt++) {
                const int n = wn + nt * 8 + r0;
                bb[nt][0] = __float_as_uint(S[brow0 * SROW + n]) ^ bmsk0;
                bb[nt][1] = __float_as_uint(S[brow1 * SROW + n]) ^ bmsk1;
            }
#pragma unroll
            for (int mt = 0; mt < 4; mt++) {
                const int m = wm + mt * 16 + r0;
                const uint32_t a0 = tf32c(S[kc * SROW + m]);
                const uint32_t a1 = tf32c(S[kc * SROW + m + 8]);
                const uint32_t a2 = __float_as_uint(S[(kc + 4) * SROW + m]);
                const uint32_t a3 = __float_as_uint(S[(kc + 4) * SROW + m + 8]);
#pragma unroll
                for (int nt = 0; nt < 4; nt++)
                    mma_tf32(acc[mt][nt], a0, a1, a2, a3, bb[nt][0], bb[nt][1]);
            }
        }
        __syncthreads();
    }

    float* out = g_Rp + (((size_t)b * KS + ks) << 14);
#pragma unroll
    for (int mt = 0; mt < 4; mt++) {
        const int m = wm + mt * 16 + r0;
#pragma unroll
        for (int nt = 0; nt < 4; nt++) {
            const int n = wn + nt * 8 + 2 * kc;
            *(float2*)&out[m * 128 + n]       = make_float2(acc[mt][nt][0], acc[mt][nt][1]);
            *(float2*)&out[(m + 8) * 128 + n] = make_float2(acc[mt][nt][2], acc[mt][nt][3]);
        }
    }
}

// ---------------- K2c: reduce split-K partials (float4) ----------------
__global__ void reduce_kernel() {
    const int idx = blockIdx.x * 256 + threadIdx.x;
    const int b = idx >> 12;
    const int e = idx & 4095;
    const float4* p = (const float4*)(g_Rp + ((size_t)b * KS << 14)) + e;
    float4 s = {0, 0, 0, 0};
#pragma unroll 8
    for (int k = 0; k < KS; k++) {
        const float4 v = p[(size_t)k << 12];
        s.x += v.x; s.y += v.y; s.z += v.z; s.w += v.w;
    }
    ((float4*)g_Rm)[idx] = s;
}

// ---------------- 256-thread reductions for eigen tail ----------------
__device__ __forceinline__ float brs256(float v, float* red) {
#pragma unroll
    for (int off = 16; off > 0; off >>= 1) v += __shfl_down_sync(0xffffffffu, v, off);
    if ((threadIdx.x & 31) == 0) red[threadIdx.x >> 5] = v;
    __syncthreads();
    float s = 0.f;
#pragma unroll
    for (int i = 0; i < 8; i++) s += red[i];
    __syncthreads();
    return s;
}
__device__ __forceinline__ float brmin256(float v, float* red) {
#pragma unroll
    for (int off = 16; off > 0; off >>= 1) v = fminf(v, __shfl_down_sync(0xffffffffu, v, off));
    if ((threadIdx.x & 31) == 0) red[threadIdx.x >> 5] = v;
    __syncthreads();
    float s = red[0];
#pragma unroll
    for (int i = 1; i < 8; i++) s = fminf(s, red[i]);
    __syncthreads();
    return s;
}
__device__ __forceinline__ float brmax256(float v, float* red) {
#pragma unroll
    for (int off = 16; off > 0; off >>= 1) v = fmaxf(v, __shfl_down_sync(0xffffffffu, v, off));
    if ((threadIdx.x & 31) == 0) red[threadIdx.x >> 5] = v;
    __syncthreads();
    float s = red[0];
#pragma unroll
    for (int i = 1; i < 8; i++) s = fmaxf(s, red[i]);
    __syncthreads();
    return s;
}

// 64-way predicated register extract (no local-memory spill)
__device__ __forceinline__ float dyn_extract(const float4* a, int idx) {
    float v = 0.0f;
    const int j4 = idx >> 2, c = idx & 3;
#pragma unroll
    for (int j = 0; j < 16; j++) {
        if (j == j4) {
            const float4 t4 = a[j];
            v = (c == 0) ? t4.x : (c == 1) ? t4.y : (c == 2) ? t4.z : t4.w;
        }
    }
    return v;
}

// ---------------- K3: register-resident Householder + split twisted Sturm ----------------
#define ASTR 132
#define SMEM_EIG ((128 * ASTR + 3 * 128 + 256 + 2 * 128 + 96 + 8) * 4)

__global__ void __launch_bounds__(256)
eigen_kernel() {
    extern __shared__ float smE[];
    float* Astage = smE;                   // 128 x ASTR (staging; later bisection scratch)
    float* xA = Astage + 128 * ASTR;       // 128
    float* xB = xA + 128;                  // 128
    float* qq = xB + 128;                  // 128
    float* pp = qq + 128;                  // 256 (half praw partials; later e2)
    float* dd = pp + 256;                  // 128
    float* ee = dd + 128;                  // 128
    float* red = ee + 128;                 // 96
    float* dsl = red + 96;                 // 2 parity slots for A[k+1][k+1]

    const int b = blockIdx.x;
    const int t = threadIdx.x;
    const int r = t & 127;
    const int h = t >> 7;
    const int w = t >> 5, lane = t & 31;
    const int cbeg = h << 6;
    const float* R = g_Rm + (size_t)b * D * D;

    // stage symmetrized matrix
    for (int i = h; i < 128; i += 2)
        Astage[i * ASTR + r] = 0.5f * (R[i * 128 + r] + R[r * 128 + i]);
    __syncthreads();

    // load register row-half + diagonal mirror
    float4 areg[16];
    {
        const float* Arow = Astage + r * ASTR + cbeg;
#pragma unroll
        for (int j = 0; j < 16; j++) areg[j] = *(const float4*)(Arow + 4 * j);
    }
    float dreg = Astage[r * ASTR + r];
    if (h == 0) xA[r] = (r > 0) ? Astage[r * ASTR] : 0.0f;
    if (t == 1) dsl[0] = Astage[1 * ASTR + 1];
    __syncthreads();

    // bootstrap praw partial
    float pnreg;
    {
        const float4* X4 = (const float4*)(xA + cbeg);
        float pa[4] = {0.f, 0.f, 0.f, 0.f};
#pragma unroll
        for (int q = 0; q < 16; q++) {
            const float4 a = areg[q], xv = X4[q];
            pa[q & 3] += a.x * xv.x + a.y * xv.y + a.z * xv.z + a.w * xv.w;
        }
        pnreg = (pa[0] + pa[1]) + (pa[2] + pa[3]);
        pp[t] = pnreg;
    }
    __syncthreads();

    for (int k = 0; k < 126; k++) {
        float* xx = (k & 1) ? xB : xA;
        float* xn = (k & 1) ? xA : xB;
        float* sA = red + (k & 1) * 32;
        float* sB = sA + 8;
        const int hk1 = (k + 1) >> 6;
        const int cidx = (k + 1) & 63;

        const float xi = xx[r];
        float ws  = (h == 0) ? xi * xi : 0.0f;
        float kv2 = xi * pnreg;
#pragma unroll
        for (int off = 16; off > 0; off >>= 1) {
            ws  += __shfl_down_sync(0xffffffffu, ws, off);
            kv2 += __shfl_down_sync(0xffffffffu, kv2, off);
        }
        if (lane == 0) { sA[w] = ws; sB[w] = kv2; }
        __syncthreads();                                  // (1)
        float sig = 0.f, S2 = 0.f;
#pragma unroll
        for (int i = 0; i < 8; i++) { sig += sA[i]; S2 += sB[i]; }
        const float x0 = xx[k + 1];
        const float nrm = sqrtf(sig);
        const float alpha = (x0 >= 0.0f) ? -nrm : nrm;
        const float H = sig - alpha * x0;
        const float invH = (H > 1e-32f) ? 1.0f / H : 0.0f;
        if (t == 0) ee[k + 1] = alpha;
        const float dk1 = dsl[k & 1];
        const float praw_k1 = pp[k + 1] + pp[k + 1 + 128];
        const float uAu = S2 - 2.0f * alpha * praw_k1 + alpha * alpha * dk1;
        const float Kc = uAu * invH * 0.5f * invH;
        const float ut = xi - ((r == k + 1) ? alpha : 0.0f);
        const float uk1 = x0 - alpha;
        const float pk1 = (praw_k1 - alpha * dk1) * invH;
        const float qk1 = pk1 - Kc * uk1;
        if (h == hk1) {                       // owner of column k+1 publishes q, xn
            const float ak1 = dyn_extract(areg, cidx);
            const float p = (r > k) ? ((pp[r] + pp[r + 128]) - alpha * ak1) * invH : 0.0f;
            const float qown = (r > k) ? (p - Kc * ut) : 0.0f;
            qq[r] = qown;
            xn[r] = (r >= k + 2) ? (ak1 - ut * qk1 - qown * uk1) : 0.0f;
        }
        __syncthreads();                                  // (2)
        const float qt = qq[r];
        float pn[4] = {0.f, 0.f, 0.f, 0.f};
        if (r > k) {
            const float4* Q4 = (const float4*)(qq + cbeg);
            const float4* X4 = (const float4*)(xx + cbeg);
            const float4* N4 = (const float4*)(xn + cbeg);
#pragma unroll
            for (int j = 0; j < 16; j++) {
                float4 a = areg[j];
                const float4 q4 = Q4[j], x4 = X4[j], n4 = N4[j];
                a.x -= ut * q4.x + qt * x4.x;
                a.y -= ut * q4.y + qt * x4.y;
                a.z -= ut * q4.z + qt * x4.z;
                a.w -= ut * q4.w + qt * x4.w;
                pn[j & 3] += a.x * n4.x + a.y * n4.y + a.z * n4.z + a.w * n4.w;
                areg[j] = a;
            }
            dreg -= ut * qt + qt * xi;        // diagonal mirror (j = r term)
            if (r == k + 1) dreg += alpha * qt;  // x-vs-u fix, only row k+1's diag matters
        }
        if (r == k + 2 && h == 0) dsl[(k + 1) & 1] = dreg;
        pnreg = (pn[0] + pn[1]) + (pn[2] + pn[3]);
        pp[t] = pnreg;
        // next iteration's barrier (1) orders the publishes
    }
    __syncthreads();

    if (h == 0) {
        dd[r] = dreg;
        if (r == 0) { ee[0] = 0.0f; ee[127] = xA[127]; }  // final xn buffer (k=125 odd -> xA)
    }
    __syncthreads();
    float* e2 = pp;
    if (h == 0) e2[r] = ee[r] * ee[r];
    float gl_in = FLT_MAX, gu_in = -FLT_MAX;
    if (h == 0) {
        const float rad = fabsf(ee[r]) + ((r < 127) ? fabsf(ee[r + 1]) : 0.0f);
        gl_in = dd[r] - rad;
        gu_in = dd[r] + rad;
    }
    const float gl = brmin256(gl_in, red + 64);
    const float gu = brmax256(gu_in, red + 64);
    __syncthreads();

    const float pivmin = fmaxf(1e-12f * fmaxf(fabsf(gl), fabsf(gu)), 1e-36f);
    float* qx0 = Astage;
    int*   cx0 = (int*)(Astage + 1024);
    float lo = gl, hi = gu;
    for (int iter = 0; iter < 26; ++iter) {
        const int par = (iter & 1) * 256;
        float* qx = qx0 + par;
        int*   cx = cx0 + par;
        const float mid = 0.5f * (lo + hi);
        if (h == 0) {
            float qf = dd[0] - mid;
            int cf = (qf < 0.0f);
#pragma unroll 3
            for (int j = 1; j <= 63; j++) {
                if (fabsf(qf) < pivmin) qf = -pivmin;
                qf = dd[j] - mid - __fdividef(e2[j], qf);
                cf += (qf < 0.0f);
            }
            if (fabsf(qf) < pivmin) qf = -pivmin;
            qx[r] = qf; cx[r] = cf;
        } else {
            float qb = dd[127] - mid;
            int cb = (qb < 0.0f);
#pragma unroll 3
            for (int i = 126; i >= 65; i--) {
                if (fabsf(qb) < pivmin) qb = -pivmin;
                qb = dd[i] - mid - __fdividef(e2[i + 1], qb);
                cb += (qb < 0.0f);
            }
            if (fabsf(qb) < pivmin) qb = -pivmin;
            qx[128 + r] = qb; cx[128 + r] = cb;
        }
        __syncthreads();
        const float qf = qx[r], qb = qx[128 + r];
        const float gam = dd[64] - mid - __fdividef(e2[64], qf) - __fdividef(e2[65], qb);
        const int cnt = cx[r] + cx[128 + r] + (gam < 0.0f);
        if (cnt > r) hi = mid; else lo = mid;
    }
    const float lam = 0.5f * (lo + hi);
    const float v = (h == 0 && lam > 0.0f) ? sqrtf(lam) : 0.0f;
    __syncthreads();
    const float s = brs256(v, red + 64);
    if (t == 0) g_partial[b] = s;
}

// ---------------- K4: mean over batch ----------------
__global__ void finalize_kernel(float* out) {
    out[0] = 0.25f * (g_partial[0] + g_partial[1] + g_partial[2] + g_partial[3]);
}

// ---------------- launch ----------------
extern "C" void kernel_launch(void* const* d_in, const int* in_sizes, int n_in,
                              void* d_out, int out_size) {
    const float* x  = (const float*)d_in[0];
    const float* J  = (const float*)d_in[1];
    const int*   ei = (const int*)d_in[2];
    const int E = in_sizes[2] / 2;
    float* out = (float*)d_out;

    cudaFuncSetAttribute(eigen_kernel,
                         cudaFuncAttributeMaxDynamicSharedMemorySize, SMEM_EIG);
    cudaFuncSetAttribute(gemm_kernel,
                         cudaFuncAttributeMaxDynamicSharedMemorySize, GSMEM);

    rowptr_kernel<<<(N_NODES + 1 + 255) / 256, 256>>>(ei, E);

    dim3 ggeo((N_NODES + 127) / 128, BATCH);
    geom_kernel<<<ggeo, 128>>>(x, ei + E);

    dim3 gbuild(N_NODES / 8, BATCH);
    build_kernel<<<gbuild, 256>>>(J, ei + E);

    dim3 ggemm(KS, BATCH);
    gemm_kernel<<<ggemm, 256, GSMEM>>>(J);
    reduce_kernel<<<BATCH * D * D / 4 / 256, 256>>>();

    eigen_kernel<<<BATCH, 256, SMEM_EIG>>>();
    finalize_kernel<<<1, 1>>>(out);
}

// round 16
// speedup vs baseline: 1.0347x; 1.0184x over previous
#include <cuda_runtime.h>
#include <math.h>
#include <float.h>
#include <stdint.h>

#define N_NODES 16384
#define D 128
#define BATCH 4
#define WPRIME (0.05f/1.05f)
#define EMAX 98304

#define KS 74
#define PAIRS (N_NODES / 2)
#define STAGES 4
#define SROW 136
#define STAGE_F (24 * SROW)
#define GSMEM (STAGES * STAGE_F * 4)

// ---------------- device scratch ----------------
__device__ float g_Rm[BATCH * D * D];
__device__ float g_Rp[(size_t)BATCH * KS * D * D];
__device__ int   g_rowptr[N_NODES + 1];
__device__ float g_partial[BATCH];
__device__ float g_pan[(size_t)BATCH * N_NODES * 1024];
__device__ float4 g_edgev[(size_t)BATCH * EMAX];
__device__ float g_geo[(size_t)BATCH * N_NODES * 12];

__device__ __forceinline__ uint32_t tf32c(float f) {
    uint32_t u; asm("cvt.rna.tf32.f32 %0, %1;" : "=r"(u) : "f"(f)); return u;
}
__device__ __forceinline__ float tf32f(float f) {
    return __uint_as_float(tf32c(f));
}

// ---------------- K1: CSR row pointers ----------------
__global__ void rowptr_kernel(const int* __restrict__ e0, int E) {
    int n = blockIdx.x * blockDim.x + threadIdx.x;
    if (n > N_NODES) return;
    int lo = 0, hi = E;
    while (lo < hi) {
        int mid = (lo + hi) >> 1;
        if (e0[mid] < n) lo = mid + 1; else hi = mid;
    }
    g_rowptr[n] = lo;
}

// ---------------- K1b: per-node geometry ----------------
__global__ void geom_kernel(const float* __restrict__ x, const int* __restrict__ e1arr) {
    const int n = blockIdx.x * blockDim.x + threadIdx.x;
    const int b = blockIdx.y;
    if (n >= N_NODES) return;

    const float* xb = x + (size_t)b * N_NODES * 3;
    const float xn0 = xb[3 * n], xn1 = xb[3 * n + 1], xn2 = xb[3 * n + 2];
    float4* ev = g_edgev + (size_t)b * EMAX;

    float deg = 0.f, s0 = 0.f, s1 = 0.f, s2 = 0.f, G = 0.f;
    float c00 = 0.f, c01 = 0.f, c02 = 0.f, c11 = 0.f, c12 = 0.f, c22 = 0.f;

    const int eBeg = g_rowptr[n], eEnd = g_rowptr[n + 1];
    for (int e = eBeg; e < eEnd; ++e) {
        const int m = e1arr[e];
        const float v0 = xn0 - xb[3 * m];
        const float v1 = xn1 - xb[3 * m + 1];
        const float v2 = xn2 - xb[3 * m + 2];
        ev[e] = make_float4(v0, v1, v2, 0.0f);
        deg += 1.0f; s0 += v0; s1 += v1; s2 += v2;
        const float vv = v0 * v0 + v1 * v1 + v2 * v2;
        G += vv;
        c00 += vv - v0 * v0; c01 -= v0 * v1; c02 -= v0 * v2;
        c11 += vv - v1 * v1; c12 -= v1 * v2; c22 += vv - v2 * v2;
    }

    const float l00 = sqrtf(c00);
    const float il00 = 1.0f / l00;
    const float l10 = c01 * il00, l20 = c02 * il00;
    const float l11 = sqrtf(c11 - l10 * l10);
    const float il11 = 1.0f / l11;
    const float l21 = (c12 - l20 * l10) * il11;
    const float l22 = sqrtf(c22 - l20 * l20 - l21 * l21);
    const float il22 = 1.0f / l22;
    const float Ginv = (G < 1e-6f) ? 0.0f : 1.0f / G;

    float* ge = g_geo + ((size_t)b * N_NODES + n) * 12;
    ge[0] = deg; ge[1] = s0; ge[2] = s1; ge[3] = s2;
    ge[4] = il00; ge[5] = l10; ge[6] = il11;
    ge[7] = l20; ge[8] = l21; ge[9] = il22;
    ge[10] = WPRIME * Ginv; ge[11] = 0.0f;
}

// ---------------- K2a: build panels — one WARP per node, float4 per lane ----------------
__global__ void __launch_bounds__(256)
build_kernel(const float* __restrict__ J, const int* __restrict__ e1arr) {
    const int b = blockIdx.y;
    const int warp = threadIdx.x >> 5;
    const int lane = threadIdx.x & 31;
    const int n = blockIdx.x * 8 + warp;
    const int c4 = lane * 4;

    const float* Jb = J + (size_t)b * N_NODES * 3 * D;
    const float4* ev = g_edgev + (size_t)b * EMAX;

    const float* JnR = Jb + (size_t)(3 * n) * D + c4;
    const float4 Jn0 = *(const float4*)(JnR);
    const float4 Jn1 = *(const float4*)(JnR + D);
    const float4 Jn2 = *(const float4*)(JnR + 2 * D);

    float4 nb0 = {0,0,0,0}, nb1 = {0,0,0,0}, nb2 = {0,0,0,0};
    float4 T0 = {0,0,0,0}, T1 = {0,0,0,0}, T2 = {0,0,0,0}, uu = {0,0,0,0};

    const int eBeg = g_rowptr[n], eEnd = g_rowptr[n + 1];
    const int degn = eEnd - eBeg;

#define ACC_NEIGH(v, m0, m1, m2)                                           \
    do {                                                                   \
        nb0.x += m0.x; nb0.y += m0.y; nb0.z += m0.z; nb0.w += m0.w;        \
        nb1.x += m1.x; nb1.y += m1.y; nb1.z += m1.z; nb1.w += m1.w;        \
        nb2.x += m2.x; nb2.y += m2.y; nb2.z += m2.z; nb2.w += m2.w;        \
        T0.x += v.y * m2.x - v.z * m1.x;  T0.y += v.y * m2.y - v.z * m1.y; \
        T0.z += v.y * m2.z - v.z * m1.z;  T0.w += v.y * m2.w - v.z * m1.w; \
        T1.x += v.z * m0.x - v.x * m2.x;  T1.y += v.z * m0.y - v.x * m2.y; \
        T1.z += v.z * m0.z - v.x * m2.z;  T1.w += v.z * m0.w - v.x * m2.w; \
        T2.x += v.x * m1.x - v.y * m0.x;  T2.y += v.x * m1.y - v.y * m0.y; \
        T2.z += v.x * m1.z - v.y * m0.z;  T2.w += v.x * m1.w - v.y * m0.w; \
        uu.x += v.x * m0.x + v.y * m1.x + v.z * m2.x;                      \
        uu.y += v.x * m0.y + v.y * m1.y + v.z * m2.y;                      \
        uu.z += v.x * m0.z + v.y * m1.z + v.z * m2.z;                      \
        uu.w += v.x * m0.w + v.y * m1.w + v.z * m2.w;                      \
    } while (0)

    if (degn == 6) {
        int mm[6];
#pragma unroll
        for (int i = 0; i < 6; i++) mm[i] = e1arr[eBeg + i];
        float4 vv6[6];
#pragma unroll
        for (int i = 0; i < 6; i++) vv6[i] = ev[eBeg + i];
#pragma unroll
        for (int i = 0; i < 6; i += 2) {
            const float* JmA = Jb + (size_t)(3 * mm[i]) * D + c4;
            const float* JmB = Jb + (size_t)(3 * mm[i + 1]) * D + c4;
            const float4 a0 = *(const float4*)(JmA);
            const float4 a1 = *(const float4*)(JmA + D);
            const float4 a2 = *(const float4*)(JmA + 2 * D);
            const float4 b0 = *(const float4*)(JmB);
            const float4 b1 = *(const float4*)(JmB + D);
            const float4 b2 = *(const float4*)(JmB + 2 * D);
            { const float4 v = vv6[i];     ACC_NEIGH(v, a0, a1, a2); }
            { const float4 v = vv6[i + 1]; ACC_NEIGH(v, b0, b1, b2); }
        }
    } else {
        for (int e = eBeg; e < eEnd; ++e) {
            const int m = e1arr[e];
            const float4 v = ev[e];
            const float* Jm = Jb + (size_t)(3 * m) * D + c4;
            const float4 m0 = *(const float4*)(Jm);
            const float4 m1 = *(const float4*)(Jm + D);
            const float4 m2 = *(const float4*)(Jm + 2 * D);
            ACC_NEIGH(v, m0, m1, m2);
        }
    }
#undef ACC_NEIGH

    const float* ge = g_geo + ((size_t)b * N_NODES + n) * 12;
    const float deg = ge[0], s0 = ge[1], s1 = ge[2], s2 = ge[3];
    const float il00 = ge[4], l10 = ge[5], il11 = ge[6];
    const float l20 = ge[7], l21 = ge[8], il22 = ge[9];
    const float wGinv = ge[10];

    float* P = g_pan + ((size_t)b * N_NODES + n) * 1024 + c4;
    float4 oZ0, oZ1, oZ2, oy, oL0, oL1, oL2, og;

#define COL(F)                                                              \
    {                                                                       \
        const float jn0 = Jn0.F, jn1 = Jn1.F, jn2 = Jn2.F;                  \
        const float LJ0 = 2.0f * (deg * jn0 - nb0.F);                       \
        const float LJ1 = 2.0f * (deg * jn1 - nb1.F);                       \
        const float LJ2 = 2.0f * (deg * jn2 - nb2.F);                       \
        const float B0 = T0.F + s2 * jn1 - s1 * jn2;                        \
        const float B1 = T1.F - s2 * jn0 + s0 * jn2;                        \
        const float B2 = T2.F + s1 * jn0 - s0 * jn1;                        \
        const float y = uu.F - (s0 * jn0 + s1 * jn1 + s2 * jn2);            \
        const float Z0 = B0 * il00;                                         \
        const float Z1 = (B1 - l10 * Z0) * il11;                            \
        const float Z2 = (B2 - l20 * Z0 - l21 * Z1) * il22;                 \
        oZ0.F = tf32f(Z0); oZ1.F = tf32f(Z1); oZ2.F = tf32f(Z2);            \
        oy.F = tf32f(y);                                                    \
        oL0.F = tf32f(LJ0); oL1.F = tf32f(LJ1); oL2.F = tf32f(LJ2);         \
        og.F = tf32f(-wGinv * y);                                           \
    }
    COL(x) COL(y) COL(z) COL(w)
#undef COL

    *(float4*)(P + 0 * 128) = oZ0;  *(float4*)(P + 1 * 128) = oZ1;
    *(float4*)(P + 2 * 128) = oZ2;  *(float4*)(P + 3 * 128) = oy;
    *(float4*)(P + 4 * 128) = oL0;  *(float4*)(P + 5 * 128) = oL1;
    *(float4*)(P + 6 * 128) = oL2;  *(float4*)(P + 7 * 128) = og;
}

// ---------------- K2b: TF32 split-K GEMM (unchanged, known good) ----------------
__device__ __forceinline__ void cp_async16(void* dst_smem, const void* src) {
    uint32_t d = (uint32_t)__cvta_generic_to_shared(dst_smem);
    asm volatile("cp.async.cg.shared.global [%0], [%1], 16;" :: "r"(d), "l"(src));
}
__device__ __forceinline__ void cp_commit() { asm volatile("cp.async.commit_group;"); }
template<int NN> __device__ __forceinline__ void cp_wait() {
    asm volatile("cp.async.wait_group %0;" :: "n"(NN));
}
__device__ __forceinline__ void mma_tf32(float* d, uint32_t a0, uint32_t a1,
                                         uint32_t a2, uint32_t a3,
                                         uint32_t b0, uint32_t b1) {
    asm volatile(
        "mma.sync.aligned.m16n8k8.row.col.f32.tf32.tf32.f32 "
        "{%0,%1,%2,%3}, {%4,%5,%6,%7}, {%8,%9}, {%0,%1,%2,%3};"
        : "+f"(d[0]), "+f"(d[1]), "+f"(d[2]), "+f"(d[3])
        : "r"(a0), "r"(a1), "r"(a2), "r"(a3), "r"(b0), "r"(b1));
}

__global__ void __launch_bounds__(256, 2)
gemm_kernel(const float* __restrict__ J) {
    extern __shared__ float smg[];

    const int b = blockIdx.y, ks = blockIdx.x;
    const int t = threadIdx.x;
    const int wid = t >> 5, lane = t & 31;
    const int wm = (wid >> 2) * 64;
    const int wn = (wid & 3) * 32;
    const int r0 = lane >> 2, kc = lane & 3;

    const int pbeg = (ks * PAIRS) / KS;
    const int pend = ((ks + 1) * PAIRS) / KS;
    const int NITv = pend - pbeg;
    const int nodeBase = 2 * pbeg;

    const float* Jb = J + (size_t)b * N_NODES * 3 * D;
    const float* Pb = g_pan + ((size_t)b * N_NODES + nodeBase) * 1024;

    for (int idx = t; idx < STAGES * 2 * SROW; idx += 256) {
        const int s = idx / (2 * SROW);
        const int rem = idx - s * 2 * SROW;
        const int row = (rem < SROW) ? 7 : 19;
        smg[s * STAGE_F + row * SROW + (rem % SROW)] = 0.0f;
    }

    const int      brow0 = (kc < 3) ? 8 + kc : 3;
    const uint32_t bmsk0 = (kc < 3) ? 0u : 0x80000000u;
    const int      brow1 = (kc < 2) ? 4 + kc : ((kc == 2) ? 11 : 7);
    const uint32_t bmsk1 = (kc < 2) ? 0x80000000u : 0u;

    float acc[4][4][4];
#pragma unroll
    for (int i = 0; i < 4; i++)
#pragma unroll
        for (int j = 0; j < 4; j++)
#pragma unroll
            for (int r = 0; r < 4; r++) acc[i][j][r] = 0.0f;

    const int prow = t >> 5;
    const int scol = (t & 31) * 4;
    const int srowP = (prow < 4) ? 3 + prow : 4 + prow;

    auto issue = [&](int it) {
        const int stg = it & (STAGES - 1);
        float* SB = smg + stg * STAGE_F;
        const float* p0 = Pb + (size_t)(2 * it) * 1024;
        cp_async16(SB + srowP * SROW + scol, p0 + t * 4);
        cp_async16(SB + (12 + srowP) * SROW + scol, p0 + 1024 + t * 4);
        if (t < 96) {
            const float* j0 = Jb + (size_t)(3 * (nodeBase + 2 * it)) * D;
            cp_async16(SB + prow * SROW + scol, j0 + t * 4);
            cp_async16(SB + (12 + prow) * SROW + scol, j0 + 384 + t * 4);
        }
    };

    for (int s = 0; s < STAGES - 1; s++) { if (s < NITv) issue(s); cp_commit(); }

    for (int it = 0; it < NITv; ++it) {
        const int stg = it & (STAGES - 1);
        if (it + STAGES - 1 < NITv) issue(it + STAGES - 1);
        cp_commit();
        cp_wait<STAGES - 1>();
        __syncthreads();

        const float* S0 = smg + stg * STAGE_F;
#pragma unroll
        for (int g = 0; g < 2; ++g) {
            const float* S = S0 + g * 12 * SROW;

            uint32_t bb[4][2];
#pragma unroll
            for (int nt = 0; nt < 4; nt++) {
                const int n = wn + nt * 8 + r0;
                bb[nt][0] = __float_as_uint(S[brow0 * SROW + n]) ^ bmsk0;
                bb[nt][1] = __float_as_uint(S[brow1 * SROW + n]) ^ bmsk1;
            }
#pragma unroll
            for (int mt = 0; mt < 4; mt++) {
                const int m = wm + mt * 16 + r0;
                const uint32_t a0 = tf32c(S[kc * SROW + m]);
                const uint32_t a1 = tf32c(S[kc * SROW + m + 8]);
                const uint32_t a2 = __float_as_uint(S[(kc + 4) * SROW + m]);
                const uint32_t a3 = __float_as_uint(S[(kc + 4) * SROW + m + 8]);
#pragma unroll
                for (int nt = 0; nt < 4; nt++)
                    mma_tf32(acc[mt][nt], a0, a1, a2, a3, bb[nt][0], bb[nt][1]);
            }
        }
        __syncthreads();
    }

    float* out = g_Rp + (((size_t)b * KS + ks) << 14);
#pragma unroll
    for (int mt = 0; mt < 4; mt++) {
        const int m = wm + mt * 16 + r0;
#pragma unroll
        for (int nt = 0; nt < 4; nt++) {
            const int n = wn + nt * 8 + 2 * kc;
            *(float2*)&out[m * 128 + n]       = make_float2(acc[mt][nt][0], acc[mt][nt][1]);
            *(float2*)&out[(m + 8) * 128 + n] = make_float2(acc[mt][nt][2], acc[mt][nt][3]);
        }
    }
}

// ---------------- K2c: reduce split-K partials (float4) ----------------
__global__ void reduce_kernel() {
    const int idx = blockIdx.x * 256 + threadIdx.x;
    const int b = idx >> 12;
    const int e = idx & 4095;
    const float4* p = (const float4*)(g_Rp + ((size_t)b * KS << 14)) + e;
    float4 s = {0, 0, 0, 0};
#pragma unroll 8
    for (int k = 0; k < KS; k++) {
        const float4 v = p[(size_t)k << 12];
        s.x += v.x; s.y += v.y; s.z += v.z; s.w += v.w;
    }
    ((float4*)g_Rm)[idx] = s;
}

// ---------------- 512-thread reductions (16 warps) ----------------
__device__ __forceinline__ float brs512(float v, float* red) {
#pragma unroll
    for (int off = 16; off > 0; off >>= 1) v += __shfl_down_sync(0xffffffffu, v, off);
    if ((threadIdx.x & 31) == 0) red[threadIdx.x >> 5] = v;
    __syncthreads();
    float s = 0.f;
#pragma unroll
    for (int i = 0; i < 16; i++) s += red[i];
    __syncthreads();
    return s;
}
__device__ __forceinline__ float brmin512(float v, float* red) {
#pragma unroll
    for (int off = 16; off > 0; off >>= 1) v = fminf(v, __shfl_down_sync(0xffffffffu, v, off));
    if ((threadIdx.x & 31) == 0) red[threadIdx.x >> 5] = v;
    __syncthreads();
    float s = red[0];
#pragma unroll
    for (int i = 1; i < 16; i++) s = fminf(s, red[i]);
    __syncthreads();
    return s;
}
__device__ __forceinline__ float brmax512(float v, float* red) {
#pragma unroll
    for (int off = 16; off > 0; off >>= 1) v = fmaxf(v, __shfl_down_sync(0xffffffffu, v, off));
    if ((threadIdx.x & 31) == 0) red[threadIdx.x >> 5] = v;
    __syncthreads();
    float s = red[0];
#pragma unroll
    for (int i = 1; i < 16; i++) s = fmaxf(s, red[i]);
    __syncthreads();
    return s;
}

// 32-way predicated register extract (8 float4 slots)
__device__ __forceinline__ float dyn_extract8(const float4* a, int idx) {
    float v = 0.0f;
    const int j4 = idx >> 2, c = idx & 3;
#pragma unroll
    for (int j = 0; j < 8; j++) {
        if (j == j4) {
            const float4 t4 = a[j];
            v = (c == 0) ? t4.x : (c == 1) ? t4.y : (c == 2) ? t4.z : t4.w;
        }
    }
    return v;
}

// ---------------- K3: quarter-row register Householder + split twisted Sturm ----------------
#define ASTR 132
#define SMEM_EIG ((128 * ASTR + 3 * 128 + 512 + 2 * 128 + 128 + 8) * 4)

__global__ void __launch_bounds__(512)
eigen_kernel() {
    extern __shared__ float smE[];
    float* Astage = smE;                   // 128 x ASTR (staging; later bisection scratch)
    float* xA = Astage + 128 * ASTR;       // 128
    float* xB = xA + 128;                  // 128
    float* qq = xB + 128;                  // 128
    float* pp = qq + 128;                  // 512 (quarter praw partials; later e2)
    float* dd = pp + 512;                  // 128
    float* ee = dd + 128;                  // 128
    float* red = ee + 128;                 // 128: loop parity banks [0..63], tail [64..]
    float* dsl = red + 128;                // 2 parity slots for A[k+1][k+1]

    const int b = blockIdx.x;
    const int t = threadIdx.x;
    const int r = t & 127;                 // row
    const int h = t >> 7;                  // quarter: cols [h*32, h*32+32)
    const int w = t >> 5, lane = t & 31;
    const int cbeg = h << 5;
    const float* R = g_Rm + (size_t)b * D * D;

    // stage symmetrized matrix
    for (int i = h; i < 128; i += 4)
        Astage[i * ASTR + r] = 0.5f * (R[i * 128 + r] + R[r * 128 + i]);
    __syncthreads();

    // register quarter-row + diagonal mirror
    float4 areg[8];
    {
        const float* Arow = Astage + r * ASTR + cbeg;
#pragma unroll
        for (int j = 0; j < 8; j++) areg[j] = *(const float4*)(Arow + 4 * j);
    }
    float dreg = Astage[r * ASTR + r];
    if (h == 0) xA[r] = (r > 0) ? Astage[r * ASTR] : 0.0f;
    if (t == 1) dsl[0] = Astage[1 * ASTR + 1];
    __syncthreads();

    // bootstrap praw quarter-partial
    float pnreg;
    {
        const float4* X4 = (const float4*)(xA + cbeg);
        float pa[4] = {0.f, 0.f, 0.f, 0.f};
#pragma unroll
        for (int q = 0; q < 8; q++) {
            const float4 a = areg[q], xv = X4[q];
            pa[q & 3] += a.x * xv.x + a.y * xv.y + a.z * xv.z + a.w * xv.w;
        }
        pnreg = (pa[0] + pa[1]) + (pa[2] + pa[3]);
        pp[t] = pnreg;
    }
    __syncthreads();

    for (int k = 0; k < 126; k++) {
        float* xx = (k & 1) ? xB : xA;
        float* xn = (k & 1) ? xA : xB;
        float* sA = red + (k & 1) * 32;
        float* sB = sA + 16;
        const int hk1 = (k + 1) >> 5;
        const int cidx = (k + 1) & 31;

        const float xi = xx[r];
        float ws  = (h == 0) ? xi * xi : 0.0f;
        float kv2 = xi * pnreg;              // quarter partial -> sums to full x.praw
#pragma unroll
        for (int off = 16; off > 0; off >>= 1) {
            ws  += __shfl_down_sync(0xffffffffu, ws, off);
            kv2 += __shfl_down_sync(0xffffffffu, kv2, off);
        }
        if (lane == 0) { sA[w] = ws; sB[w] = kv2; }
        __syncthreads();                                  // (1)
        float sig = 0.f, S2 = 0.f;
#pragma unroll
        for (int i = 0; i < 16; i++) { sig += sA[i]; S2 += sB[i]; }
        const float x0 = xx[k + 1];
        const float nrm = sqrtf(sig);
        const float alpha = (x0 >= 0.0f) ? -nrm : nrm;
        const float H = sig - alpha * x0;
        const float invH = (H > 1e-32f) ? 1.0f / H : 0.0f;
        if (t == 0) ee[k + 1] = alpha;
        const float dk1 = dsl[k & 1];
        const float praw_k1 = pp[k + 1] + pp[k + 1 + 128] + pp[k + 1 + 256] + pp[k + 1 + 384];
        const float uAu = S2 - 2.0f * alpha * praw_k1 + alpha * alpha * dk1;
        const float Kc = uAu * invH * 0.5f * invH;
        const float ut = xi - ((r == k + 1) ? alpha : 0.0f);
        const float uk1 = x0 - alpha;
        const float pk1 = (praw_k1 - alpha * dk1) * invH;
        const float qk1 = pk1 - Kc * uk1;
        if (h == hk1) {                       // owner quarter publishes q, xn
            const float ak1 = dyn_extract8(areg, cidx);
            const float p = (r > k) ?
                ((pp[r] + pp[r + 128] + pp[r + 256] + pp[r + 384]) - alpha * ak1) * invH : 0.0f;
            const float qown = (r > k) ? (p - Kc * ut) : 0.0f;
            qq[r] = qown;
            xn[r] = (r >= k + 2) ? (ak1 - ut * qk1 - qown * uk1) : 0.0f;
        }
        __syncthreads();                                  // (2)
        const float qt = qq[r];
        float pn[4] = {0.f, 0.f, 0.f, 0.f};
        if (r > k) {
            const float4* Q4 = (const float4*)(qq + cbeg);
            const float4* X4 = (const float4*)(xx + cbeg);
            const float4* N4 = (const float4*)(xn + cbeg);
#pragma unroll
            for (int j = 0; j < 8; j++) {
                float4 a = areg[j];
                const float4 q4 = Q4[j], x4 = X4[j], n4 = N4[j];
                a.x -= ut * q4.x + qt * x4.x;
                a.y -= ut * q4.y + qt * x4.y;
                a.z -= ut * q4.z + qt * x4.z;
                a.w -= ut * q4.w + qt * x4.w;
                pn[j & 3] += a.x * n4.x + a.y * n4.y + a.z * n4.z + a.w * n4.w;
                areg[j] = a;
            }
            dreg -= ut * qt + qt * xi;            // diagonal mirror (consistent per quarter)
            if (r == k + 1) dreg += alpha * qt;   // x-vs-u fix for row k+1 diag
        }
        if (r == k + 2 && h == 0) dsl[(k + 1) & 1] = dreg;
        pnreg = (pn[0] + pn[1]) + (pn[2] + pn[3]);
        pp[t] = pnreg;
        // next iteration's barrier (1) orders the publishes
    }
    __syncthreads();

    if (h == 0) {
        dd[r] = dreg;
        if (r == 0) { ee[0] = 0.0f; ee[127] = xA[127]; }  // final xn buffer (k=125 odd -> xA)
    }
    __syncthreads();
    float* e2 = pp;
    if (h == 0) e2[r] = ee[r] * ee[r];
    float gl_in = FLT_MAX, gu_in = -FLT_MAX;
    if (h == 0) {
        const float rad = fabsf(ee[r]) + ((r < 127) ? fabsf(ee[r + 1]) : 0.0f);
        gl_in = dd[r] - rad;
        gu_in = dd[r] + rad;
    }
    const float gl = brmin512(gl_in, red + 64);
    const float gu = brmax512(gu_in, red + 64);
    __syncthreads();

    const float pivmin = fmaxf(1e-12f * fmaxf(fabsf(gl), fabsf(gu)), 1e-36f);
    float* qx0 = Astage;
    int*   cx0 = (int*)(Astage + 1024);
    float lo = gl, hi = gu;
    for (int iter = 0; iter < 26; ++iter) {
        const int par = (iter & 1) * 256;
        float* qx = qx0 + par;
        int*   cx = cx0 + par;
        const float mid = 0.5f * (lo + hi);
        if (h == 0) {
            float qf = dd[0] - mid;
            int cf = (qf < 0.0f);
#pragma unroll 3
            for (int j = 1; j <= 63; j++) {
                if (fabsf(qf) < pivmin) qf = -pivmin;
                qf = dd[j] - mid - __fdividef(e2[j], qf);
                cf += (qf < 0.0f);
            }
            if (fabsf(qf) < pivmin) qf = -pivmin;
            qx[r] = qf; cx[r] = cf;
        } else if (h == 1) {
            float qb = dd[127] - mid;
            int cb = (qb < 0.0f);
#pragma unroll 3
            for (int i = 126; i >= 65; i--) {
                if (fabsf(qb) < pivmin) qb = -pivmin;
                qb = dd[i] - mid - __fdividef(e2[i + 1], qb);
                cb += (qb < 0.0f);
            }
            if (fabsf(qb) < pivmin) qb = -pivmin;
            qx[128 + r] = qb; cx[128 + r] = cb;
        }
        __syncthreads();
        const float qf = qx[r], qb = qx[128 + r];
        const float gam = dd[64] - mid - __fdividef(e2[64], qf) - __fdividef(e2[65], qb);
        const int cnt = cx[r] + cx[128 + r] + (gam < 0.0f);
        if (cnt > r) hi = mid; else lo = mid;
    }
    const float lam = 0.5f * (lo + hi);
    const float v = (h == 0 && lam > 0.0f) ? sqrtf(lam) : 0.0f;
    __syncthreads();
    const float s = brs512(v, red + 64);
    if (t == 0) g_partial[b] = s;
}

// ---------------- K4: mean over batch ----------------
__global__ void finalize_kernel(float* out) {
    out[0] = 0.25f * (g_partial[0] + g_partial[1] + g_partial[2] + g_partial[3]);
}

// ---------------- launch ----------------
extern "C" void kernel_launch(void* const* d_in, const int* in_sizes, int n_in,
                              void* d_out, int out_size) {
    const float* x  = (const float*)d_in[0];
    const float* J  = (const float*)d_in[1];
    const int*   ei = (const int*)d_in[2];
    const int E = in_sizes[2] / 2;
    float* out = (float*)d_out;

    cudaFuncSetAttribute(eigen_kernel,
                         cudaFuncAttributeMaxDynamicSharedMemorySize, SMEM_EIG);
    cudaFuncSetAttribute(gemm_kernel,
                         cudaFuncAttributeMaxDynamicSharedMemorySize, GSMEM);

    rowptr_kernel<<<(N_NODES + 1 + 255) / 256, 256>>>(ei, E);

    dim3 ggeo((N_NODES + 127) / 128, BATCH);
    geom_kernel<<<ggeo, 128>>>(x, ei + E);

    dim3 gbuild(N_NODES / 8, BATCH);
    build_kernel<<<gbuild, 256>>>(J, ei + E);

    dim3 ggemm(KS, BATCH);
    gemm_kernel<<<ggemm, 256, GSMEM>>>(J);
    reduce_kernel<<<BATCH * D * D / 4 / 256, 256>>>();

    eigen_kernel<<<BATCH, 512, SMEM_EIG>>>();
    finalize_kernel<<<1, 1>>>(out);
}